// round 5
// baseline (speedup 1.0000x reference)
#include <cuda_runtime.h>

#define Bsz 128
#define Tsz 2048
#define Fsz 64
#define Usz 128
#define G4  512          // 4*U
#define CH  256          // time-chunk length
#define NCH (Tsz / CH)   // 8 chunks

// Chunked scratch (allocation-free contract: __device__ globals). ~145 MB total.
__device__ float g_xw1c[(size_t)CH * Bsz * G4];   // 64 MB: x@W1+b1 for chunk, [tc][b][512]
__device__ float g_h1c [(size_t)CH * Bsz * Usz];  // 16 MB: layer-1 h for chunk, [tc][b][128]
__device__ float g_xw2c[(size_t)CH * Bsz * G4];   // 64 MB: h1@W2+b2 for chunk
// Carried recurrent state (h,c per layer), [b][u]
__device__ float g_h1s[Bsz * Usz];
__device__ float g_c1s[Bsz * Usz];
__device__ float g_h2s[Bsz * Usz];
__device__ float g_c2s[Bsz * Usz];

__device__ __forceinline__ float sigmoidf(float x) {
    return __fdividef(1.0f, 1.0f + __expf(-x));
}

// ---------------------------------------------------------------------------
// k_xw1: g_xw1c[tc,b,g] = b1[g] + sum_f x[b,t0+tc,f] * W1[f,g]
// One W1 column per thread in registers; 4 (t,b)-rows per iteration.
// ---------------------------------------------------------------------------
__global__ __launch_bounds__(512, 1) void k_xw1(const float* __restrict__ x,
                                                const float* __restrict__ W1,
                                                const float* __restrict__ b1,
                                                int t0) {
    const int g = threadIdx.x;
    float wc[Fsz];
#pragma unroll
    for (int f = 0; f < Fsz; f++) wc[f] = W1[f * G4 + g];
    const float bias = b1[g];

    __shared__ float xs[4][Fsz];
    const int total = CH * Bsz;
    for (int base = blockIdx.x * 4; base < total; base += gridDim.x * 4) {
        if (threadIdx.x < 4 * Fsz) {
            int rr = threadIdx.x / Fsz, f = threadIdx.x % Fsz;
            int row = base + rr;                  // row = tc*B + b
            int t = t0 + row / Bsz, b = row % Bsz;
            xs[rr][f] = x[((size_t)b * Tsz + t) * Fsz + f];
        }
        __syncthreads();
        float a0 = bias, a1 = bias, a2 = bias, a3 = bias;
#pragma unroll
        for (int f = 0; f < Fsz; f += 4) {
            float4 x0 = *(const float4*)&xs[0][f];
            float4 x1 = *(const float4*)&xs[1][f];
            float4 x2 = *(const float4*)&xs[2][f];
            float4 x3 = *(const float4*)&xs[3][f];
            float w0 = wc[f], w1 = wc[f + 1], w2 = wc[f + 2], w3 = wc[f + 3];
            a0 += x0.x * w0 + x0.y * w1 + x0.z * w2 + x0.w * w3;
            a1 += x1.x * w0 + x1.y * w1 + x1.z * w2 + x1.w * w3;
            a2 += x2.x * w0 + x2.y * w1 + x2.z * w2 + x2.w * w3;
            a3 += x3.x * w0 + x3.y * w1 + x3.z * w2 + x3.w * w3;
        }
        g_xw1c[(size_t)(base + 0) * G4 + g] = a0;
        g_xw1c[(size_t)(base + 1) * G4 + g] = a1;
        g_xw1c[(size_t)(base + 2) * G4 + g] = a2;
        g_xw1c[(size_t)(base + 3) * G4 + g] = a3;
        __syncthreads();
    }
}

// ---------------------------------------------------------------------------
// k_xw2: g_xw2c[tc,b,g] = b2[g] + sum_u g_h1c[tc,b,u] * W2[u,g]
// K=128: 64 rows of the W2 column in registers, 64 rows in smem.
// 4 (t,b)-rows per iteration to amortize smem weight reads.
// ---------------------------------------------------------------------------
#define XW2_RREG 64
#define XW2_RSM  (Usz - XW2_RREG)   // 64

__global__ __launch_bounds__(512, 1) void k_xw2(const float* __restrict__ W2,
                                                const float* __restrict__ b2) {
    extern __shared__ float sm[];
    float* w2s = sm;                      // [XW2_RSM][512]
    float* xs  = sm + XW2_RSM * G4;       // [4][128]
    const int g = threadIdx.x;

    float wc[XW2_RREG];
#pragma unroll
    for (int j = 0; j < XW2_RREG; j++) wc[j] = W2[j * G4 + g];
    for (int idx = threadIdx.x; idx < XW2_RSM * G4; idx += blockDim.x)
        w2s[idx] = W2[XW2_RREG * G4 + idx];   // rows 64..127, contiguous
    const float bias = b2[g];
    __syncthreads();

    const int total = CH * Bsz;
    for (int base = blockIdx.x * 4; base < total; base += gridDim.x * 4) {
        {
            int rr = threadIdx.x / Usz, u = threadIdx.x % Usz;   // 512 = 4*128
            xs[rr * Usz + u] = g_h1c[(size_t)(base + rr) * Usz + u];
        }
        __syncthreads();
        float a0 = bias, a1 = bias, a2 = bias, a3 = bias;
#pragma unroll
        for (int j = 0; j < XW2_RREG; j += 4) {
            float4 x0 = *(const float4*)&xs[j];
            float4 x1 = *(const float4*)&xs[Usz + j];
            float4 x2 = *(const float4*)&xs[2 * Usz + j];
            float4 x3 = *(const float4*)&xs[3 * Usz + j];
            float w0 = wc[j], w1 = wc[j + 1], w2 = wc[j + 2], w3 = wc[j + 3];
            a0 += x0.x * w0 + x0.y * w1 + x0.z * w2 + x0.w * w3;
            a1 += x1.x * w0 + x1.y * w1 + x1.z * w2 + x1.w * w3;
            a2 += x2.x * w0 + x2.y * w1 + x2.z * w2 + x2.w * w3;
            a3 += x3.x * w0 + x3.y * w1 + x3.z * w2 + x3.w * w3;
        }
#pragma unroll
        for (int jj = 0; jj < XW2_RSM; jj += 4) {
            float4 x0 = *(const float4*)&xs[XW2_RREG + jj];
            float4 x1 = *(const float4*)&xs[Usz + XW2_RREG + jj];
            float4 x2 = *(const float4*)&xs[2 * Usz + XW2_RREG + jj];
            float4 x3 = *(const float4*)&xs[3 * Usz + XW2_RREG + jj];
            float w0 = w2s[(jj + 0) * G4 + g];
            float w1 = w2s[(jj + 1) * G4 + g];
            float w2 = w2s[(jj + 2) * G4 + g];
            float w3 = w2s[(jj + 3) * G4 + g];
            a0 += x0.x * w0 + x0.y * w1 + x0.z * w2 + x0.w * w3;
            a1 += x1.x * w0 + x1.y * w1 + x1.z * w2 + x1.w * w3;
            a2 += x2.x * w0 + x2.y * w1 + x2.z * w2 + x2.w * w3;
            a3 += x3.x * w0 + x3.y * w1 + x3.z * w2 + x3.w * w3;
        }
        g_xw2c[(size_t)(base + 0) * G4 + g] = a0;
        g_xw2c[(size_t)(base + 1) * G4 + g] = a1;
        g_xw2c[(size_t)(base + 2) * G4 + g] = a2;
        g_xw2c[(size_t)(base + 3) * G4 + g] = a3;
        __syncthreads();
    }
}

// ---------------------------------------------------------------------------
// Recurrent kernel over one time chunk: one CTA per batch element, 512 thr.
// Thread g owns z-column g. Weights: rows 0..RREG-1 in registers (1 float
// each), rows RREG..127 in smem. Two K-split accumulators for ILP. Each
// thread applies its own gate activation before the smem exchange, so the
// tid<128 combine phase is pure FMA. State carried between chunk launches.
// ---------------------------------------------------------------------------
#define RREG 64
#define RSM  (Usz - RREG)   // 64

template <bool LAYER1>
__global__ __launch_bounds__(512, 1) void lstm_rec(const float* __restrict__ Uw,
                                                   const float* __restrict__ Wd,
                                                   const float* __restrict__ bd,
                                                   float* __restrict__ out,
                                                   int first, int last) {
    extern __shared__ float sm[];
    float* ws   = sm;                    // [RSM][512]
    float* hbuf = sm + RSM * G4;         // 128 floats
    float* zbuf = hbuf + Usz;            // 512 floats (activated gate values)

    const int g = threadIdx.x;
    const int b = blockIdx.x;
    const int gate = g >> 7;             // 0:i 1:f 2:g(relu) 3:o
    const float* __restrict__ xw = LAYER1 ? (const float*)g_xw1c : (const float*)g_xw2c;
    float* __restrict__ hs = LAYER1 ? g_h1s : g_h2s;
    float* __restrict__ cs = LAYER1 ? g_c1s : g_c2s;

    // Load weights: one column per thread
    float wr[RREG];
#pragma unroll
    for (int r = 0; r < RREG; r++)
        wr[r] = Uw[r * G4 + g];
    for (int idx = g; idx < RSM * G4; idx += 512)
        ws[idx] = Uw[RREG * G4 + idx];   // rows 64..127, contiguous

    float c = 0.0f;
    if (g < Usz) {
        hbuf[g] = first ? 0.0f : hs[b * Usz + g];
        if (!first) c = cs[b * Usz + g];
    }
    __syncthreads();

    float cur = xw[(size_t)b * G4 + g];  // tc = 0

    for (int tc = 0; tc < CH; tc++) {
        float nxt = 0.0f;
        if (tc + 1 < CH)
            nxt = xw[((size_t)(tc + 1) * Bsz + b) * G4 + g];

        float a0 = cur, a1 = 0.0f;
        // Register-resident rows 0..63 (split 32/32 over two accumulators)
#pragma unroll
        for (int r = 0; r < 32; r += 4) {
            float4 h4 = *(const float4*)&hbuf[r];
            a0 += h4.x * wr[r] + h4.y * wr[r + 1] + h4.z * wr[r + 2] + h4.w * wr[r + 3];
        }
#pragma unroll
        for (int r = 32; r < RREG; r += 4) {
            float4 h4 = *(const float4*)&hbuf[r];
            a1 += h4.x * wr[r] + h4.y * wr[r + 1] + h4.z * wr[r + 2] + h4.w * wr[r + 3];
        }
        // Smem-resident rows 64..127 (split 32/32)
#pragma unroll
        for (int r = 0; r < 32; r += 4) {
            float4 h4 = *(const float4*)&hbuf[RREG + r];
            float w0 = ws[(r + 0) * G4 + g];
            float w1 = ws[(r + 1) * G4 + g];
            float w2 = ws[(r + 2) * G4 + g];
            float w3 = ws[(r + 3) * G4 + g];
            a0 += h4.x * w0 + h4.y * w1 + h4.z * w2 + h4.w * w3;
        }
#pragma unroll
        for (int r = 32; r < RSM; r += 4) {
            float4 h4 = *(const float4*)&hbuf[RREG + r];
            float w0 = ws[(r + 0) * G4 + g];
            float w1 = ws[(r + 1) * G4 + g];
            float w2 = ws[(r + 2) * G4 + g];
            float w3 = ws[(r + 3) * G4 + g];
            a1 += h4.x * w0 + h4.y * w1 + h4.z * w2 + h4.w * w3;
        }
        float z = a0 + a1;
        // Apply this column's activation here (spreads MUFU over all 16 warps)
        z = (gate == 2) ? fmaxf(z, 0.0f) : sigmoidf(z);
        zbuf[g] = z;
        __syncthreads();

        if (g < Usz) {
            float ig = zbuf[g];
            float fg = zbuf[Usz + g];
            float gg = zbuf[2 * Usz + g];
            float og = zbuf[3 * Usz + g];
            c = fg * c + ig * gg;
            float h = og * fmaxf(c, 0.0f);
            hbuf[g] = h;
            if (LAYER1)
                g_h1c[((size_t)tc * Bsz + b) * Usz + g] = h;
        }
        __syncthreads();
        cur = nxt;
    }

    // Persist state for next chunk
    if (g < Usz) {
        hs[b * Usz + g] = hbuf[g];
        cs[b * Usz + g] = c;
    }

    if (!LAYER1 && last) {
        // Final dense: out[b] = sum_u h[u]*Wd[u] + bd
        zbuf[g] = (g < Usz) ? hbuf[g] * Wd[g] : 0.0f;
        __syncthreads();
        if (g == 0) {
            float s = bd[0];
#pragma unroll 8
            for (int u = 0; u < Usz; u++) s += zbuf[u];
            out[b] = s;
        }
    }
}

// ---------------------------------------------------------------------------
extern "C" void kernel_launch(void* const* d_in, const int* in_sizes, int n_in,
                              void* d_out, int out_size) {
    const float* x  = (const float*)d_in[0];
    const float* W1 = (const float*)d_in[1];
    const float* U1 = (const float*)d_in[2];
    const float* b1 = (const float*)d_in[3];
    const float* W2 = (const float*)d_in[4];
    const float* U2 = (const float*)d_in[5];
    const float* b2 = (const float*)d_in[6];
    const float* Wd = (const float*)d_in[7];
    const float* bd = (const float*)d_in[8];
    float* out = (float*)d_out;

    const size_t sm_xw2 = (size_t)(XW2_RSM * G4 + 4 * Usz) * sizeof(float);   // ~133 KB
    const size_t sm_rec = (size_t)(RSM * G4 + Usz + G4) * sizeof(float);      // ~134 KB

    (void)cudaFuncSetAttribute((const void*)k_xw2,
                         cudaFuncAttributeMaxDynamicSharedMemorySize, (int)sm_xw2);
    (void)cudaFuncSetAttribute((const void*)lstm_rec<true>,
                         cudaFuncAttributeMaxDynamicSharedMemorySize, (int)sm_rec);
    (void)cudaFuncSetAttribute((const void*)lstm_rec<false>,
                         cudaFuncAttributeMaxDynamicSharedMemorySize, (int)sm_rec);

    for (int k = 0; k < NCH; k++) {
        const int first = (k == 0);
        const int last  = (k == NCH - 1);
        // layer-1 input projection for this chunk
        k_xw1<<<148, 512>>>(x, W1, b1, k * CH);
        // layer-1 recurrence for this chunk (stores h1 chunk + state)
        lstm_rec<true><<<Bsz, 512, sm_rec>>>(U1, Wd, bd, out, first, last);
        // layer-2 input projection for this chunk
        k_xw2<<<148, 512, sm_xw2>>>(W2, b2);
        // layer-2 recurrence for this chunk (+ final dense on last chunk)
        lstm_rec<false><<<Bsz, 512, sm_rec>>>(U2, Wd, bd, out, first, last);
    }
}

// round 6
// speedup vs baseline: 1.2911x; 1.2911x over previous
#include <cuda_runtime.h>

#define Bsz 128
#define Tsz 2048
#define Fsz 64
#define Usz 128
#define G4  512          // 4*U
#define CH  256          // time-chunk length
#define NCH (Tsz / CH)   // 8 chunks

// Chunked scratch (allocation-free contract: __device__ globals). ~145 MB total.
__device__ float g_xw1c[(size_t)CH * Bsz * G4];   // 64 MB: x@W1+b1 for chunk, [tc][b][512]
__device__ float g_h1c [(size_t)CH * Bsz * Usz];  // 16 MB: layer-1 h for chunk, [tc][b][128]
__device__ float g_xw2c[(size_t)CH * Bsz * G4];   // 64 MB: h1@W2+b2 for chunk
// Carried recurrent state (h,c per layer), [b][u]
__device__ float g_h1s[Bsz * Usz];
__device__ float g_c1s[Bsz * Usz];
__device__ float g_h2s[Bsz * Usz];
__device__ float g_c2s[Bsz * Usz];

__device__ __forceinline__ float sigmoidf(float x) {
    return __fdividef(1.0f, 1.0f + __expf(-x));
}

// ---- packed f32x2 helpers (Blackwell) -------------------------------------
__device__ __forceinline__ unsigned long long pk2(float lo, float hi) {
    unsigned long long r;
    asm("mov.b64 %0, {%1, %2};" : "=l"(r) : "f"(lo), "f"(hi));
    return r;
}
__device__ __forceinline__ void ffma2(unsigned long long& acc,
                                      unsigned long long a,
                                      unsigned long long b) {
    asm("fma.rn.f32x2 %0, %1, %2, %0;" : "+l"(acc) : "l"(a), "l"(b));
}
__device__ __forceinline__ float hsum2(unsigned long long a) {
    float lo, hi;
    asm("mov.b64 {%0, %1}, %2;" : "=f"(lo), "=f"(hi) : "l"(a));
    return lo + hi;
}
__device__ __forceinline__ unsigned long long add2(unsigned long long a,
                                                   unsigned long long b) {
    unsigned long long r;
    asm("add.rn.f32x2 %0, %1, %2;" : "=l"(r) : "l"(a), "l"(b));
    return r;
}

// ---------------------------------------------------------------------------
// k_xw1: g_xw1c[tc,b,g] = b1[g] + sum_f x[b,t0+tc,f] * W1[f,g]
// ---------------------------------------------------------------------------
__global__ __launch_bounds__(512, 1) void k_xw1(const float* __restrict__ x,
                                                const float* __restrict__ W1,
                                                const float* __restrict__ b1,
                                                int t0) {
    const int g = threadIdx.x;
    float wc[Fsz];
#pragma unroll
    for (int f = 0; f < Fsz; f++) wc[f] = W1[f * G4 + g];
    const float bias = b1[g];

    __shared__ float xs[4][Fsz];
    const int total = CH * Bsz;
    for (int base = blockIdx.x * 4; base < total; base += gridDim.x * 4) {
        if (threadIdx.x < 4 * Fsz) {
            int rr = threadIdx.x / Fsz, f = threadIdx.x % Fsz;
            int row = base + rr;                  // row = tc*B + b
            int t = t0 + row / Bsz, b = row % Bsz;
            xs[rr][f] = x[((size_t)b * Tsz + t) * Fsz + f];
        }
        __syncthreads();
        float a0 = bias, a1 = bias, a2 = bias, a3 = bias;
#pragma unroll
        for (int f = 0; f < Fsz; f += 4) {
            float4 x0 = *(const float4*)&xs[0][f];
            float4 x1 = *(const float4*)&xs[1][f];
            float4 x2 = *(const float4*)&xs[2][f];
            float4 x3 = *(const float4*)&xs[3][f];
            float w0 = wc[f], w1 = wc[f + 1], w2 = wc[f + 2], w3 = wc[f + 3];
            a0 += x0.x * w0 + x0.y * w1 + x0.z * w2 + x0.w * w3;
            a1 += x1.x * w0 + x1.y * w1 + x1.z * w2 + x1.w * w3;
            a2 += x2.x * w0 + x2.y * w1 + x2.z * w2 + x2.w * w3;
            a3 += x3.x * w0 + x3.y * w1 + x3.z * w2 + x3.w * w3;
        }
        g_xw1c[(size_t)(base + 0) * G4 + g] = a0;
        g_xw1c[(size_t)(base + 1) * G4 + g] = a1;
        g_xw1c[(size_t)(base + 2) * G4 + g] = a2;
        g_xw1c[(size_t)(base + 3) * G4 + g] = a3;
        __syncthreads();
    }
}

// ---------------------------------------------------------------------------
// k_xw2: g_xw2c[tc,b,g] = b2[g] + sum_u g_h1c[tc,b,u] * W2[u,g]
// ---------------------------------------------------------------------------
#define XW2_RREG 64
#define XW2_RSM  (Usz - XW2_RREG)   // 64

__global__ __launch_bounds__(512, 1) void k_xw2(const float* __restrict__ W2,
                                                const float* __restrict__ b2) {
    extern __shared__ float sm[];
    float* w2s = sm;                      // [XW2_RSM][512]
    float* xs  = sm + XW2_RSM * G4;       // [4][128]
    const int g = threadIdx.x;

    float wc[XW2_RREG];
#pragma unroll
    for (int j = 0; j < XW2_RREG; j++) wc[j] = W2[j * G4 + g];
    for (int idx = threadIdx.x; idx < XW2_RSM * G4; idx += blockDim.x)
        w2s[idx] = W2[XW2_RREG * G4 + idx];   // rows 64..127, contiguous
    const float bias = b2[g];
    __syncthreads();

    const int total = CH * Bsz;
    for (int base = blockIdx.x * 4; base < total; base += gridDim.x * 4) {
        {
            int rr = threadIdx.x / Usz, u = threadIdx.x % Usz;   // 512 = 4*128
            xs[rr * Usz + u] = g_h1c[(size_t)(base + rr) * Usz + u];
        }
        __syncthreads();
        float a0 = bias, a1 = bias, a2 = bias, a3 = bias;
#pragma unroll
        for (int j = 0; j < XW2_RREG; j += 4) {
            float4 x0 = *(const float4*)&xs[j];
            float4 x1 = *(const float4*)&xs[Usz + j];
            float4 x2 = *(const float4*)&xs[2 * Usz + j];
            float4 x3 = *(const float4*)&xs[3 * Usz + j];
            float w0 = wc[j], w1 = wc[j + 1], w2 = wc[j + 2], w3 = wc[j + 3];
            a0 += x0.x * w0 + x0.y * w1 + x0.z * w2 + x0.w * w3;
            a1 += x1.x * w0 + x1.y * w1 + x1.z * w2 + x1.w * w3;
            a2 += x2.x * w0 + x2.y * w1 + x2.z * w2 + x2.w * w3;
            a3 += x3.x * w0 + x3.y * w1 + x3.z * w2 + x3.w * w3;
        }
#pragma unroll
        for (int jj = 0; jj < XW2_RSM; jj += 4) {
            float4 x0 = *(const float4*)&xs[XW2_RREG + jj];
            float4 x1 = *(const float4*)&xs[Usz + XW2_RREG + jj];
            float4 x2 = *(const float4*)&xs[2 * Usz + XW2_RREG + jj];
            float4 x3 = *(const float4*)&xs[3 * Usz + XW2_RREG + jj];
            float w0 = w2s[(jj + 0) * G4 + g];
            float w1 = w2s[(jj + 1) * G4 + g];
            float w2 = w2s[(jj + 2) * G4 + g];
            float w3 = w2s[(jj + 3) * G4 + g];
            a0 += x0.x * w0 + x0.y * w1 + x0.z * w2 + x0.w * w3;
            a1 += x1.x * w0 + x1.y * w1 + x1.z * w2 + x1.w * w3;
            a2 += x2.x * w0 + x2.y * w1 + x2.z * w2 + x2.w * w3;
            a3 += x3.x * w0 + x3.y * w1 + x3.z * w2 + x3.w * w3;
        }
        g_xw2c[(size_t)(base + 0) * G4 + g] = a0;
        g_xw2c[(size_t)(base + 1) * G4 + g] = a1;
        g_xw2c[(size_t)(base + 2) * G4 + g] = a2;
        g_xw2c[(size_t)(base + 3) * G4 + g] = a3;
        __syncthreads();
    }
}

// ---------------------------------------------------------------------------
// Recurrent kernel over one time chunk. One CTA / batch element, 256 threads.
// Thread g owns z-columns (2g, 2g+1). f32x2 packed FMA over row pairs:
//   rows 0..RREC-1  : register-resident packed pairs (wrA/wrB, u64 each)
//   rows RREC..127  : smem, pre-packed as (wA_r0,wA_r1,wB_r0,wB_r1) float4
// h broadcast from smem as double2 (2 packed row-pairs per LDS.128).
// ---------------------------------------------------------------------------
#define RREC 80              // rows in registers
#define RPAIR (RREC / 2)     // 40 packed pairs
#define RSMM (Usz - RREC)    // 48 rows in smem
#define SPAIR (RSMM / 2)     // 24 packed pairs

template <bool LAYER1>
__global__ __launch_bounds__(256, 1) void lstm_rec(const float* __restrict__ Uw,
                                                   const float* __restrict__ Wd,
                                                   const float* __restrict__ bd,
                                                   float* __restrict__ out,
                                                   int first, int last) {
    extern __shared__ float sm[];
    float* ws   = sm;                          // SPAIR * 256 float4s = SPAIR*1024 floats
    float* hbuf = sm + SPAIR * 1024;           // 128 floats (16B aligned)
    float* zbuf = hbuf + Usz;                  // 512 floats (activated gates)

    const int g = threadIdx.x;                 // 0..255, owns cols 2g, 2g+1
    const int b = blockIdx.x;
    const int gate = g >> 6;                   // 0:i 1:f 2:g(relu) 3:o
    const float* __restrict__ xw = LAYER1 ? (const float*)g_xw1c : (const float*)g_xw2c;
    float* __restrict__ hs = LAYER1 ? g_h1s : g_h2s;
    float* __restrict__ cs = LAYER1 ? g_c1s : g_c2s;

    // Register weights: rows 0..RREC-1 packed by row pairs, per column.
    unsigned long long wrA[RPAIR], wrB[RPAIR];
#pragma unroll
    for (int p = 0; p < RPAIR; p++) {
        wrA[p] = pk2(Uw[(2 * p) * G4 + 2 * g],     Uw[(2 * p + 1) * G4 + 2 * g]);
        wrB[p] = pk2(Uw[(2 * p) * G4 + 2 * g + 1], Uw[(2 * p + 1) * G4 + 2 * g + 1]);
    }
    // Smem weights: rows RREC..127, packed (wA_r0, wA_r1, wB_r0, wB_r1).
    for (int i = g; i < SPAIR * 256; i += 256) {
        int p = i >> 8, q = i & 255;
        int r0 = RREC + 2 * p;
        ((float4*)ws)[i] = make_float4(Uw[r0 * G4 + 2 * q], Uw[(r0 + 1) * G4 + 2 * q],
                                       Uw[r0 * G4 + 2 * q + 1], Uw[(r0 + 1) * G4 + 2 * q + 1]);
    }

    float c = 0.0f;
    if (g < Usz) {
        hbuf[g] = first ? 0.0f : hs[b * Usz + g];
        if (!first) c = cs[b * Usz + g];
    }
    __syncthreads();

    float2 cur = *(const float2*)&xw[(size_t)b * G4 + 2 * g];  // tc = 0

    const double2* hb2 = (const double2*)hbuf;     // hb2[k] = rows 4k..4k+3
    const double2* wsd = (const double2*)ws;       // wsd[p*256+g] = (pairA, pairB)

    for (int tc = 0; tc < CH; tc++) {
        float2 nxt = make_float2(0.0f, 0.0f);
        if (tc + 1 < CH)
            nxt = *(const float2*)&xw[((size_t)(tc + 1) * Bsz + b) * G4 + 2 * g];

        unsigned long long accA0 = 0ull, accA1 = 0ull, accB0 = 0ull, accB1 = 0ull;
        // rows 0..RREC-1 (register weights): RPAIR/2 double2 h loads
#pragma unroll
        for (int k = 0; k < RPAIR / 2; k++) {
            double2 hd = hb2[k];
            unsigned long long h01 = __double_as_longlong(hd.x);
            unsigned long long h23 = __double_as_longlong(hd.y);
            ffma2(accA0, h01, wrA[2 * k]);
            ffma2(accB0, h01, wrB[2 * k]);
            ffma2(accA1, h23, wrA[2 * k + 1]);
            ffma2(accB1, h23, wrB[2 * k + 1]);
        }
        // rows RREC..127 (smem weights): SPAIR/2 iterations
#pragma unroll
        for (int k = 0; k < SPAIR / 2; k++) {
            double2 hd = hb2[RPAIR / 2 + k];
            unsigned long long h01 = __double_as_longlong(hd.x);
            unsigned long long h23 = __double_as_longlong(hd.y);
            double2 w0 = wsd[(2 * k) * 256 + g];
            double2 w1 = wsd[(2 * k + 1) * 256 + g];
            ffma2(accA0, h01, __double_as_longlong(w0.x));
            ffma2(accB0, h01, __double_as_longlong(w0.y));
            ffma2(accA1, h23, __double_as_longlong(w1.x));
            ffma2(accB1, h23, __double_as_longlong(w1.y));
        }
        float zA = cur.x + hsum2(add2(accA0, accA1));
        float zB = cur.y + hsum2(add2(accB0, accB1));
        if (gate == 2) { zA = fmaxf(zA, 0.0f); zB = fmaxf(zB, 0.0f); }
        else           { zA = sigmoidf(zA);    zB = sigmoidf(zB);    }
        *(float2*)&zbuf[2 * g] = make_float2(zA, zB);
        __syncthreads();

        if (g < Usz) {
            float ig = zbuf[g];
            float fg = zbuf[Usz + g];
            float gg = zbuf[2 * Usz + g];
            float og = zbuf[3 * Usz + g];
            c = fg * c + ig * gg;
            float h = og * fmaxf(c, 0.0f);
            hbuf[g] = h;
            if (LAYER1)
                g_h1c[((size_t)tc * Bsz + b) * Usz + g] = h;
        }
        __syncthreads();
        cur = nxt;
    }

    // Persist state for next chunk
    if (g < Usz) {
        hs[b * Usz + g] = hbuf[g];
        cs[b * Usz + g] = c;
    }

    if (!LAYER1 && last) {
        // Final dense: out[b] = sum_u h[u]*Wd[u] + bd
        zbuf[g] = (g < Usz) ? hbuf[g] * Wd[g] : 0.0f;
        __syncthreads();
        if (g == 0) {
            float s = bd[0];
#pragma unroll 8
            for (int u = 0; u < Usz; u++) s += zbuf[u];
            out[b] = s;
        }
    }
}

// ---------------------------------------------------------------------------
extern "C" void kernel_launch(void* const* d_in, const int* in_sizes, int n_in,
                              void* d_out, int out_size) {
    const float* x  = (const float*)d_in[0];
    const float* W1 = (const float*)d_in[1];
    const float* U1 = (const float*)d_in[2];
    const float* b1 = (const float*)d_in[3];
    const float* W2 = (const float*)d_in[4];
    const float* U2 = (const float*)d_in[5];
    const float* b2 = (const float*)d_in[6];
    const float* Wd = (const float*)d_in[7];
    const float* bd = (const float*)d_in[8];
    float* out = (float*)d_out;

    const size_t sm_xw2 = (size_t)(XW2_RSM * G4 + 4 * Usz) * sizeof(float);    // ~133 KB
    const size_t sm_rec = (size_t)(SPAIR * 1024 + Usz + G4) * sizeof(float);   // ~101 KB

    (void)cudaFuncSetAttribute((const void*)k_xw2,
                         cudaFuncAttributeMaxDynamicSharedMemorySize, (int)sm_xw2);
    (void)cudaFuncSetAttribute((const void*)lstm_rec<true>,
                         cudaFuncAttributeMaxDynamicSharedMemorySize, (int)sm_rec);
    (void)cudaFuncSetAttribute((const void*)lstm_rec<false>,
                         cudaFuncAttributeMaxDynamicSharedMemorySize, (int)sm_rec);

    for (int k = 0; k < NCH; k++) {
        const int first = (k == 0);
        const int last  = (k == NCH - 1);
        // layer-1 input projection for this chunk
        k_xw1<<<148, 512>>>(x, W1, b1, k * CH);
        // layer-1 recurrence for this chunk (stores h1 chunk + state)
        lstm_rec<true><<<Bsz, 256, sm_rec>>>(U1, Wd, bd, out, first, last);
        // layer-2 input projection for this chunk
        k_xw2<<<148, 512, sm_xw2>>>(W2, b2);
        // layer-2 recurrence for this chunk (+ final dense on last chunk)
        lstm_rec<false><<<Bsz, 256, sm_rec>>>(U2, Wd, bd, out, first, last);
    }
}